// round 9
// baseline (speedup 1.0000x reference)
#include <cuda_runtime.h>
#include <cstdint>

// ---------------- problem constants (fixed by setup_inputs) ----------------
#define F_DIM   1024
#define KSEL    4
#define FRM_MAX 2048
#define C_MAX   100352

// ---------------- GEMM tiling ----------------
#define BM 64      // queries per block tile
#define BN 256     // candidates per block tile (four 64-col quarter tiles)
#define BK 16      // k-slab
#define TM 4       // rows per thread
#define TN 16      // cols per thread (4 x float4 quarter-tiles)
#define NSLICES 19 // 32 x 19 = 608 CTAs = 4 exact waves at occ 1
#define A_PITCH 20 // padded smem row (floats)

// ---------------- device scratch (no allocations allowed) ----------------
__device__ float g_invn[C_MAX];
__device__ float g_pv[(size_t)FRM_MAX * NSLICES * 16 * KSEL];
__device__ int   g_pi[(size_t)FRM_MAX * NSLICES * 16 * KSEL];

// ---------------- helpers ----------------
__device__ __forceinline__ void cp_async16(void* smem, const void* gmem) {
    unsigned saddr = (unsigned)__cvta_generic_to_shared(smem);
    asm volatile("cp.async.cg.shared.global [%0], [%1], 16;\n"
                 :: "r"(saddr), "l"(gmem));
}
__device__ __forceinline__ void cp_async_commit() {
    asm volatile("cp.async.commit_group;\n" ::);
}
__device__ __forceinline__ void cp_async_wait_all() {
    asm volatile("cp.async.wait_group 0;\n" ::);
}

// packed fp32x2 FMA (Blackwell FFMA2): d = a*b + d, lanewise exact fp32 FMA
__device__ __forceinline__ void ffma2(unsigned long long& d,
                                      unsigned long long a,
                                      unsigned long long b) {
    asm("fma.rn.f32x2 %0, %1, %2, %0;" : "+l"(d) : "l"(a), "l"(b));
}
__device__ __forceinline__ unsigned long long pack2(float lo, float hi) {
    unsigned long long r;
    asm("mov.b64 %0, {%1, %2};" : "=l"(r) : "f"(lo), "f"(hi));
    return r;
}
__device__ __forceinline__ float2 unpack2(unsigned long long v) {
    float2 r;
    asm("mov.b64 {%0, %1}, %2;" : "=f"(r.x), "=f"(r.y) : "l"(v));
    return r;
}

// insert (s, c) into descending top-4 (strict >, keeps earlier index on ties)
__device__ __forceinline__ void top4_insert(float s, int c, float v[KSEL], int ix[KSEL]) {
#pragma unroll
    for (int p = 0; p < KSEL; p++) {
        if (s > v[p]) {
#pragma unroll
            for (int q = KSEL - 1; q > p; q--) { v[q] = v[q - 1]; ix[q] = ix[q - 1]; }
            v[p] = s; ix[p] = c;
            break;
        }
    }
}

// ---------------- kernel 1: inverse norms of matching_set rows ----------------
__global__ void norms_kernel(const float* __restrict__ M, int C) {
    int row  = blockIdx.x * 8 + (threadIdx.x >> 5);
    int lane = threadIdx.x & 31;
    if (row >= C) return;
    const float4* p = (const float4*)(M + (size_t)row * F_DIM);
    float s = 0.f;
#pragma unroll
    for (int i = 0; i < F_DIM / 4 / 32; i++) {
        float4 v = p[lane + i * 32];
        s += v.x * v.x + v.y * v.y + v.z * v.z + v.w * v.w;
    }
#pragma unroll
    for (int o = 16; o > 0; o >>= 1) s += __shfl_xor_sync(0xffffffffu, s, o);
    if (lane == 0) g_invn[row] = rsqrtf(s);
}

// ---------------- kernel 2: tiled GEMM (FFMA2, BN=256) + fused top-4 ----------------
__global__ void __launch_bounds__(256, 1)
knn_partial_kernel(const float* __restrict__ Q, const float* __restrict__ M,
                   int FRM, int C) {
    __shared__ __align__(16) float As[2][BM * A_PITCH];   // [row][k] padded
    __shared__ __align__(16) float Bs[2][BK * BN];        // [k][col] transposed

    const int tid = threadIdx.x;
    const int tx  = tid & 15;   // candidate micro (4 quarter-tiles of float4)
    const int ty  = tid >> 4;   // query micro (4 rows)
    const int by  = blockIdx.x;
    const int sl  = blockIdx.y;

    const int tiles_total = (C + BN - 1) / BN;
    const int t0 = (int)((long long)sl       * tiles_total / NSLICES);
    const int t1 = (int)((long long)(sl + 1) * tiles_total / NSLICES);

    // A loader: 4 threads/row, one float4 each
    const int arow = tid >> 2;
    const int acol = (tid & 3) * 4;
    int aq = by * BM + arow; if (aq >= FRM) aq = FRM - 1;
    const float* Ag = Q + (size_t)aq * F_DIM + acol;

    // B loader: 1 thread/row, four float4 each (register-staged transpose)
    const int brow = tid;             // 0..255

    float tv[TM][KSEL];
    int   ti[TM][KSEL];
#pragma unroll
    for (int i = 0; i < TM; i++)
#pragma unroll
        for (int p = 0; p < KSEL; p++) { tv[i][p] = -3.4e38f; ti[i][p] = 0; }

    for (int ct = t0; ct < t1; ct++) {
        const int c0 = ct * BN;
        const bool bvalid = (c0 + brow) < C;
        const float* Bg = M + (size_t)(c0 + brow) * F_DIM;

        // packed accumulators: acc2[i][p] holds 2 adjacent candidate columns
        unsigned long long acc2[TM][8];
#pragma unroll
        for (int i = 0; i < TM; i++)
#pragma unroll
            for (int p = 0; p < 8; p++) acc2[i][p] = 0ull;

        // ---- preload k-slab 0 ----
        cp_async16(&As[0][arow * A_PITCH + acol], Ag);
        cp_async_commit();
        {
            float4 br[4];
            if (bvalid) {
#pragma unroll
                for (int h = 0; h < 4; h++) br[h] = *(const float4*)(Bg + h * 4);
            } else {
#pragma unroll
                for (int h = 0; h < 4; h++) br[h] = make_float4(0, 0, 0, 0);
            }
#pragma unroll
            for (int h = 0; h < 4; h++)
#pragma unroll
                for (int j = 0; j < 4; j++)
                    Bs[0][(h * 4 + j) * BN + brow] = ((const float*)&br[h])[j];
        }
        cp_async_wait_all();
        __syncthreads();

        const int KT = F_DIM / BK;  // 64
        for (int kt = 0; kt < KT; kt++) {
            const int buf = kt & 1, nbuf = buf ^ 1;
            float4 nB[4];
            const bool more = (kt + 1 < KT);
            if (more) {
                cp_async16(&As[nbuf][arow * A_PITCH + acol], Ag + (kt + 1) * BK);
                cp_async_commit();
                const float* Bg2 = Bg + (kt + 1) * BK;
                if (bvalid) {
#pragma unroll
                    for (int h = 0; h < 4; h++) nB[h] = *(const float4*)(Bg2 + h * 4);
                } else {
#pragma unroll
                    for (int h = 0; h < 4; h++) nB[h] = make_float4(0, 0, 0, 0);
                }
            }
#pragma unroll
            for (int kk = 0; kk < BK; kk++) {
                // duplicated a pairs (one MOV each; fills FFMA2 idle issue slots)
                unsigned long long ad[TM];
#pragma unroll
                for (int i = 0; i < TM; i++) {
                    float a = As[buf][(ty * TM + i) * A_PITCH + kk];
                    ad[i] = pack2(a, a);
                }
                // b pairs arrive packed from 4x LDS.128 (quarter-tile layout)
                unsigned long long bp[8];
#pragma unroll
                for (int qt = 0; qt < 4; qt++) {
                    ulonglong2 bl = *(const ulonglong2*)&Bs[buf][kk * BN + qt * 64 + tx * 4];
                    bp[qt * 2]     = bl.x;
                    bp[qt * 2 + 1] = bl.y;
                }
#pragma unroll
                for (int i = 0; i < TM; i++)
#pragma unroll
                    for (int p = 0; p < 8; p++)
                        ffma2(acc2[i][p], ad[i], bp[p]);
            }
            if (more) {
#pragma unroll
                for (int h = 0; h < 4; h++)
#pragma unroll
                    for (int j = 0; j < 4; j++)
                        Bs[nbuf][(h * 4 + j) * BN + brow] = ((const float*)&nB[h])[j];
            }
            cp_async_wait_all();
            __syncthreads();
        }

        // ---- fused epilogue: similarity = dot * inv_norm, update running top-4 ----
#pragma unroll
        for (int p = 0; p < 8; p++) {
            const int qt = p >> 1;
            const int nbase = qt * 64 + tx * 4 + (p & 1) * 2;
#pragma unroll
            for (int i = 0; i < TM; i++) {
                float2 d = unpack2(acc2[i][p]);
                int c = c0 + nbase;
                if (c < C)     top4_insert(d.x * g_invn[c],     c,     tv[i], ti[i]);
                if (c + 1 < C) top4_insert(d.y * g_invn[c + 1], c + 1, tv[i], ti[i]);
            }
        }
    }

    // ---- write per-(thread, slice) partial top-4 ----
#pragma unroll
    for (int i = 0; i < TM; i++) {
        const int q = by * BM + ty * TM + i;
        if (q < FRM) {
            size_t base = (((size_t)q * NSLICES + sl) * 16 + tx) * KSEL;
#pragma unroll
            for (int p = 0; p < KSEL; p++) { g_pv[base + p] = tv[i][p]; g_pi[base + p] = ti[i][p]; }
        }
    }
}

// ---------------- kernel 3: merge partials, gather synth rows, average ----------------
__global__ void merge_gather_kernel(const float* __restrict__ S, float* __restrict__ out,
                                    int FRM, int C) {
    __shared__ float sv[32 * KSEL];
    __shared__ int   si[32 * KSEL];
    __shared__ int   fidx[KSEL];

    const int q   = blockIdx.x;
    const int tid = threadIdx.x;
    const int E   = NSLICES * 16 * KSEL;   // partial entries per query

    if (tid < 32) {
        float v[KSEL]; int ix[KSEL];
#pragma unroll
        for (int p = 0; p < KSEL; p++) { v[p] = -3.4e38f; ix[p] = 0; }
        const size_t base = (size_t)q * E;
        for (int e = tid; e < E; e += 32)
            top4_insert(g_pv[base + e], g_pi[base + e], v, ix);
#pragma unroll
        for (int p = 0; p < KSEL; p++) { sv[tid * KSEL + p] = v[p]; si[tid * KSEL + p] = ix[p]; }
    }
    __syncthreads();
    if (tid == 0) {
        float v[KSEL]; int ix[KSEL];
#pragma unroll
        for (int p = 0; p < KSEL; p++) { v[p] = -3.4e38f; ix[p] = 0; }
        for (int e = 0; e < 32 * KSEL; e++) top4_insert(sv[e], si[e], v, ix);
#pragma unroll
        for (int p = 0; p < KSEL; p++) fidx[p] = ix[p];
    }
    __syncthreads();

    const float4* s0 = (const float4*)(S + (size_t)fidx[0] * F_DIM);
    const float4* s1 = (const float4*)(S + (size_t)fidx[1] * F_DIM);
    const float4* s2 = (const float4*)(S + (size_t)fidx[2] * F_DIM);
    const float4* s3 = (const float4*)(S + (size_t)fidx[3] * F_DIM);
    float4* o = (float4*)(out + (size_t)q * F_DIM);

    for (int pos = tid; pos < F_DIM / 4; pos += blockDim.x) {
        float4 a = s0[pos], b = s1[pos], c = s2[pos], d = s3[pos];
        float4 r;
        r.x = (a.x + b.x + c.x + d.x) * 0.25f;
        r.y = (a.y + b.y + c.y + d.y) * 0.25f;
        r.z = (a.z + b.z + c.z + d.z) * 0.25f;
        r.w = (a.w + b.w + c.w + d.w) * 0.25f;
        o[pos] = r;
    }
}

// ---------------- launch ----------------
extern "C" void kernel_launch(void* const* d_in, const int* in_sizes, int n_in,
                              void* d_out, int out_size) {
    const float* Q = (const float*)d_in[0];   // query_seq    (FRM, F)
    const float* M = (const float*)d_in[1];   // matching_set (C, F)
    const float* S = (const float*)d_in[2];   // synth_set    (C, F)
    // d_in[3] = topk (int32, fixed at 4 by setup_inputs) — hardcoded as KSEL
    float* out = (float*)d_out;

    const int FRM = in_sizes[0] / F_DIM;
    const int C   = in_sizes[1] / F_DIM;

    norms_kernel<<<(C + 7) / 8, 256>>>(M, C);

    dim3 g2((FRM + BM - 1) / BM, NSLICES);
    knn_partial_kernel<<<g2, 256>>>(Q, M, FRM, C);

    merge_gather_kernel<<<FRM, 256>>>(S, out, FRM, C);
}

// round 13
// speedup vs baseline: 2.0781x; 2.0781x over previous
#include <cuda_runtime.h>
#include <cuda_bf16.h>
#include <cstdint>

// ---------------- problem constants ----------------
#define F_DIM   1024
#define KSEL    4
#define FRM_MAX 2048
#define C_MAX   100352          // 784 tiles of 128 >= ceil(100000/128)=782

// ---------------- mma tiling ----------------
#define MT      128             // queries per CTA tile
#define NT      128             // candidates per CTA tile
#define KC      64              // K elems per smem chunk (64 bf16 = 128B row)
#define NSLICE  19              // 16 x 19 = 304 CTAs
#define NPROD   6               // limb products kept: 00,01,10,11,02,20
#define TILE_B  (128 * 128)     // 16KB per limb tile (128 rows x 128B)
#define SMEM_DYN (2 * 6 * TILE_B + 1024)
#define STAGE_PITCH 129         // f32 pitch for epilogue staging (conflict-free)

#define SWZ128(off) ((off) ^ (((off) >> 3) & 0x70))

// ---------------- device scratch (static: no allocations allowed) ----------------
__device__ float         g_invn[C_MAX];
__device__ __nv_bfloat16 g_qs[3][(size_t)FRM_MAX * F_DIM];   // Q limbs
__device__ __nv_bfloat16 g_bs[3][(size_t)C_MAX * F_DIM];     // M limbs (tail rows stay 0)
__device__ float g_pv[(size_t)FRM_MAX * NSLICE * KSEL];
__device__ int   g_pi[(size_t)FRM_MAX * NSLICE * KSEL];

// limb-product list (dropped terms contribute ~2^-26 each; cos err ~1e-6)
__device__ __constant__ int c_prA[NPROD] = {0, 0, 1, 1, 0, 2};
__device__ __constant__ int c_prB[NPROD] = {0, 1, 0, 1, 2, 0};

// ---------------- helpers ----------------
__device__ __forceinline__ uint32_t smem_u32(const void* p) {
    return (uint32_t)__cvta_generic_to_shared(p);
}
__device__ __forceinline__ void cp16(uint32_t dst, const void* src) {
    asm volatile("cp.async.cg.shared.global [%0], [%1], 16;" :: "r"(dst), "l"(src));
}
__device__ __forceinline__ void cp_commit() { asm volatile("cp.async.commit_group;" ::); }
__device__ __forceinline__ void cp_wait0()  { asm volatile("cp.async.wait_group 0;" ::: "memory"); }
__device__ __forceinline__ void cp_wait1()  { asm volatile("cp.async.wait_group 1;" ::: "memory"); }

__device__ __forceinline__ void ldmx4(uint32_t& r0, uint32_t& r1, uint32_t& r2, uint32_t& r3,
                                      uint32_t addr) {
    asm volatile("ldmatrix.sync.aligned.m8n8.x4.shared.b16 {%0,%1,%2,%3}, [%4];"
                 : "=r"(r0), "=r"(r1), "=r"(r2), "=r"(r3) : "r"(addr));
}
__device__ __forceinline__ void ldmx2(uint32_t& r0, uint32_t& r1, uint32_t addr) {
    asm volatile("ldmatrix.sync.aligned.m8n8.x2.shared.b16 {%0,%1}, [%2];"
                 : "=r"(r0), "=r"(r1) : "r"(addr));
}
__device__ __forceinline__ void mma_bf16(float d[4], const uint32_t a[4], const uint32_t b[2]) {
    asm volatile("mma.sync.aligned.m16n8k16.row.col.f32.bf16.bf16.f32 "
                 "{%0,%1,%2,%3}, {%4,%5,%6,%7}, {%8,%9}, {%0,%1,%2,%3};"
                 : "+f"(d[0]), "+f"(d[1]), "+f"(d[2]), "+f"(d[3])
                 : "r"(a[0]), "r"(a[1]), "r"(a[2]), "r"(a[3]), "r"(b[0]), "r"(b[1]));
}

__device__ __forceinline__ void top4_insert(float s, int c, float v[KSEL], int ix[KSEL]) {
#pragma unroll
    for (int p = 0; p < KSEL; p++) {
        if (s > v[p]) {
#pragma unroll
            for (int q = KSEL - 1; q > p; q--) { v[q] = v[q - 1]; ix[q] = ix[q - 1]; }
            v[p] = s; ix[p] = c;
            break;
        }
    }
}

// ---------------- kernel 0: 3-limb bf16 split ----------------
__global__ void split_kernel(const float* __restrict__ X,
                             __nv_bfloat16* __restrict__ d0,
                             __nv_bfloat16* __restrict__ d1,
                             __nv_bfloat16* __restrict__ d2, size_t n4) {
    size_t i = (size_t)blockIdx.x * blockDim.x + threadIdx.x;
    if (i >= n4) return;
    float4 x = ((const float4*)X)[i];
    __nv_bfloat16 h0[4], h1[4], h2[4];
    const float* xs = (const float*)&x;
#pragma unroll
    for (int j = 0; j < 4; j++) {
        float v = xs[j];
        __nv_bfloat16 a0 = __float2bfloat16(v);
        float r1 = v - __bfloat162float(a0);
        __nv_bfloat16 a1 = __float2bfloat16(r1);
        float r2 = r1 - __bfloat162float(a1);
        h0[j] = a0; h1[j] = a1; h2[j] = __float2bfloat16(r2);
    }
    __nv_bfloat162* p0 = (__nv_bfloat162*)d0 + i * 2;
    __nv_bfloat162* p1 = (__nv_bfloat162*)d1 + i * 2;
    __nv_bfloat162* p2 = (__nv_bfloat162*)d2 + i * 2;
    __nv_bfloat162 t;
    t.x = h0[0]; t.y = h0[1]; p0[0] = t;  t.x = h0[2]; t.y = h0[3]; p0[1] = t;
    t.x = h1[0]; t.y = h1[1]; p1[0] = t;  t.x = h1[2]; t.y = h1[3]; p1[1] = t;
    t.x = h2[0]; t.y = h2[1]; p2[0] = t;  t.x = h2[2]; t.y = h2[3]; p2[1] = t;
}

// ---------------- kernel 1: inverse norms ----------------
__global__ void norms_kernel(const float* __restrict__ M, int C) {
    int row  = blockIdx.x * 8 + (threadIdx.x >> 5);
    int lane = threadIdx.x & 31;
    if (row >= C) return;
    const float4* p = (const float4*)(M + (size_t)row * F_DIM);
    float s = 0.f;
#pragma unroll
    for (int i = 0; i < F_DIM / 4 / 32; i++) {
        float4 v = p[lane + i * 32];
        s += v.x * v.x + v.y * v.y + v.z * v.z + v.w * v.w;
    }
#pragma unroll
    for (int o = 16; o > 0; o >>= 1) s += __shfl_xor_sync(0xffffffffu, s, o);
    if (lane == 0) g_invn[row] = rsqrtf(s);
}

// ---------------- kernel 2: mma.sync bf16x6 GEMM + fused top-4 ----------------
__global__ void __launch_bounds__(256, 1)
knn_mma_kernel(int FRM, int C) {
    extern __shared__ __align__(16) char dsm[];
    __shared__ float sinv[NT];

    const int tid  = threadIdx.x;
    const int wid  = tid >> 5;
    const int lane = tid & 31;
    const int wr   = wid >> 2;        // warp row   (0..1) -> 64 query rows
    const int wc   = wid & 3;         // warp col   (0..3) -> 32 candidate cols
    const int mt   = blockIdx.x;
    const int sl   = blockIdx.y;

    // align dynamic smem base to 1KB for the SW128 swizzle
    const uint32_t dsm_u   = smem_u32(dsm);
    const uint32_t tilebase = (dsm_u + 1023u) & ~1023u;
    float* stagef = (float*)(dsm + (tilebase - dsm_u));   // epilogue staging (reuses tiles)

    const int tiles_total = (C + NT - 1) / NT;
    const int t0 = (int)((long long)sl       * tiles_total / NSLICE);
    const int t1 = (int)((long long)(sl + 1) * tiles_total / NSLICE);

    // per-thread ldmatrix address components
    const int a_row = lane & 15;            // A: row within m16 tile
    const int a_sel = lane >> 4;            // A: k-half (0/1)
    const int b_row = lane & 7;             // B: row within n8 tile
    const int b_sel = (lane >> 3) & 1;      // B: k-half (0/1)

    // running top-4: thread t<128 owns query row mt*128+t
    float tv[KSEL]; int ti[KSEL];
#pragma unroll
    for (int p = 0; p < KSEL; p++) { tv[p] = -3.4e38f; ti[p] = 0; }

    for (int ct = t0; ct < t1; ct++) {
        const int c0 = ct * NT;

        // ---- load one K-chunk slab (6 limb tiles, 96KB) into buffer `buf` ----
        auto load_slab = [&](int kc, int buf) {
            const uint32_t bb = tilebase + (uint32_t)(buf * 6) * TILE_B;
#pragma unroll
            for (int t = 0; t < 24; t++) {
                int idx   = tid + t * 256;        // 0..6143
                int tile  = idx >> 10;            // 0-2: A limbs, 3-5: B limbs
                int ch    = idx & 1023;
                int row   = ch >> 3;              // 0..127
                int col16 = ch & 7;               // 16B unit in 128B row
                uint32_t dst = bb + (uint32_t)tile * TILE_B
                             + SWZ128((uint32_t)(row * 128 + col16 * 16));
                const __nv_bfloat16* src;
                if (tile < 3) {
                    int qr = mt * MT + row; if (qr >= FRM) qr = FRM - 1;
                    src = &g_qs[tile][(size_t)qr * F_DIM + kc * KC + col16 * 8];
                } else {
                    src = &g_bs[tile - 3][(size_t)(c0 + row) * F_DIM + kc * KC + col16 * 8];
                }
                cp16(dst, src);
            }
            cp_commit();
        };

        float acc[4][4][4];
#pragma unroll
        for (int mi = 0; mi < 4; mi++)
#pragma unroll
            for (int ni = 0; ni < 4; ni++)
#pragma unroll
                for (int r = 0; r < 4; r++) acc[mi][ni][r] = 0.f;

        load_slab(0, 0);

        const int NKC = F_DIM / KC;   // 16
        for (int kc = 0; kc < NKC; kc++) {
            const int buf = kc & 1;
            const bool more = (kc + 1 < NKC);
            if (more) { load_slab(kc + 1, buf ^ 1); cp_wait1(); }
            else      { cp_wait0(); }
            __syncthreads();           // slab `buf` visible to all warps

            const uint32_t bb = tilebase + (uint32_t)(buf * 6) * TILE_B;
#pragma unroll
            for (int pr = 0; pr < NPROD; pr++) {
                const uint32_t Abase = bb + (uint32_t)c_prA[pr] * TILE_B;
                const uint32_t Bbase = bb + (uint32_t)(3 + c_prB[pr]) * TILE_B;
#pragma unroll
                for (int ks = 0; ks < 4; ks++) {          // 4 x k16 per 64-chunk
                    uint32_t af[4][4];
#pragma unroll
                    for (int mi = 0; mi < 4; mi++) {
                        int row = wr * 64 + mi * 16 + a_row;
                        int chk = ks * 2 + a_sel;
                        ldmx4(af[mi][0], af[mi][1], af[mi][2], af[mi][3],
                              Abase + SWZ128((uint32_t)(row * 128 + chk * 16)));
                    }
                    uint32_t bf[4][2];
#pragma unroll
                    for (int ni = 0; ni < 4; ni++) {
                        int row = wc * 32 + ni * 8 + b_row;
                        int chk = ks * 2 + b_sel;
                        ldmx2(bf[ni][0], bf[ni][1],
                              Bbase + SWZ128((uint32_t)(row * 128 + chk * 16)));
                    }
#pragma unroll
                    for (int mi = 0; mi < 4; mi++)
#pragma unroll
                        for (int ni = 0; ni < 4; ni++)
                            mma_bf16(acc[mi][ni], af[mi], bf[ni]);
                }
            }
            __syncthreads();           // all reads of `buf` done before it is refilled
        }

        // ---- epilogue: stage D in smem (pitch 129), scan rows, update top-4 ----
        if (tid < NT) sinv[tid] = g_invn[c0 + tid];
#pragma unroll
        for (int mi = 0; mi < 4; mi++) {
            int R0 = wr * 64 + mi * 16 + (lane >> 2);
#pragma unroll
            for (int ni = 0; ni < 4; ni++) {
                int Cc = wc * 32 + ni * 8 + 2 * (lane & 3);
                stagef[R0 * STAGE_PITCH + Cc]           = acc[mi][ni][0];
                stagef[R0 * STAGE_PITCH + Cc + 1]       = acc[mi][ni][1];
                stagef[(R0 + 8) * STAGE_PITCH + Cc]     = acc[mi][ni][2];
                stagef[(R0 + 8) * STAGE_PITCH + Cc + 1] = acc[mi][ni][3];
            }
        }
        __syncthreads();

        if (tid < MT) {
            const float* rowp = stagef + tid * STAGE_PITCH;
#pragma unroll 4
            for (int j = 0; j < NT; j++) {
                int gc = c0 + j;
                if (gc < C) top4_insert(rowp[j] * sinv[j], gc, tv, ti);
            }
        }
        __syncthreads();   // staging fully read before next tile's loads overwrite it
    }

    // ---- write per-(query, slice) top-4 partials ----
    const int q = mt * MT + tid;
    if (tid < MT && q < FRM) {
        size_t base = ((size_t)q * NSLICE + sl) * KSEL;
#pragma unroll
        for (int p = 0; p < KSEL; p++) { g_pv[base + p] = tv[p]; g_pi[base + p] = ti[p]; }
    }
}

// ---------------- kernel 3: merge partials, gather synth rows, average ----------------
__global__ void merge_gather_kernel(const float* __restrict__ S, float* __restrict__ out,
                                    int FRM, int C) {
    __shared__ float sv[32 * KSEL];
    __shared__ int   si[32 * KSEL];
    __shared__ int   fidx[KSEL];

    const int q   = blockIdx.x;
    const int tid = threadIdx.x;
    const int E   = NSLICE * KSEL;   // 76 partial entries per query

    if (tid < 32) {
        float v[KSEL]; int ix[KSEL];
#pragma unroll
        for (int p = 0; p < KSEL; p++) { v[p] = -3.4e38f; ix[p] = 0; }
        const size_t base = (size_t)q * E;
        for (int e = tid; e < E; e += 32)
            top4_insert(g_pv[base + e], g_pi[base + e], v, ix);
#pragma unroll
        for (int p = 0; p < KSEL; p++) { sv[tid * KSEL + p] = v[p]; si[tid * KSEL + p] = ix[p]; }
    }
    __syncthreads();
    if (tid == 0) {
        float v[KSEL]; int ix[KSEL];
#pragma unroll
        for (int p = 0; p < KSEL; p++) { v[p] = -3.4e38f; ix[p] = 0; }
        for (int e = 0; e < 32 * KSEL; e++) top4_insert(sv[e], si[e], v, ix);
#pragma unroll
        for (int p = 0; p < KSEL; p++) fidx[p] = ix[p];
    }
    __syncthreads();

    const float4* s0 = (const float4*)(S + (size_t)fidx[0] * F_DIM);
    const float4* s1 = (const float4*)(S + (size_t)fidx[1] * F_DIM);
    const float4* s2 = (const float4*)(S + (size_t)fidx[2] * F_DIM);
    const float4* s3 = (const float4*)(S + (size_t)fidx[3] * F_DIM);
    float4* o = (float4*)(out + (size_t)q * F_DIM);

    for (int pos = tid; pos < F_DIM / 4; pos += blockDim.x) {
        float4 a = s0[pos], b = s1[pos], c = s2[pos], d = s3[pos];
        float4 r;
        r.x = (a.x + b.x + c.x + d.x) * 0.25f;
        r.y = (a.y + b.y + c.y + d.y) * 0.25f;
        r.z = (a.z + b.z + c.z + d.z) * 0.25f;
        r.w = (a.w + b.w + c.w + d.w) * 0.25f;
        o[pos] = r;
    }
}

// ---------------- launch ----------------
extern "C" void kernel_launch(void* const* d_in, const int* in_sizes, int n_in,
                              void* d_out, int out_size) {
    const float* Q = (const float*)d_in[0];   // query_seq    (FRM, F)
    const float* M = (const float*)d_in[1];   // matching_set (C, F)
    const float* S = (const float*)d_in[2];   // synth_set    (C, F)
    float* out = (float*)d_out;

    const int FRM = in_sizes[0] / F_DIM;
    const int C   = in_sizes[1] / F_DIM;

    cudaFuncSetAttribute(knn_mma_kernel, cudaFuncAttributeMaxDynamicSharedMemorySize, SMEM_DYN);

    norms_kernel<<<(C + 7) / 8, 256>>>(M, C);

    __nv_bfloat16 *q0, *b0;
    cudaGetSymbolAddress((void**)&q0, g_qs);
    cudaGetSymbolAddress((void**)&b0, g_bs);
    __nv_bfloat16 *q1 = q0 + (size_t)FRM_MAX * F_DIM;
    __nv_bfloat16 *q2 = q1 + (size_t)FRM_MAX * F_DIM;
    __nv_bfloat16 *b1 = b0 + (size_t)C_MAX * F_DIM;
    __nv_bfloat16 *b2 = b1 + (size_t)C_MAX * F_DIM;

    size_t nm4 = (size_t)C * F_DIM / 4;
    size_t nq4 = (size_t)FRM * F_DIM / 4;
    split_kernel<<<(unsigned)((nm4 + 255) / 256), 256>>>(M, b0, b1, b2, nm4);
    split_kernel<<<(unsigned)((nq4 + 255) / 256), 256>>>(Q, q0, q1, q2, nq4);

    dim3 g2((FRM + MT - 1) / MT, NSLICE);
    knn_mma_kernel<<<g2, 256, SMEM_DYN>>>(FRM, C);

    merge_gather_kernel<<<FRM, 256>>>(S, out, FRM, C);
}

// round 14
// speedup vs baseline: 3.2831x; 1.5798x over previous
#include <cuda_runtime.h>
#include <cuda_fp16.h>
#include <cstdint>

// ---------------- problem constants ----------------
#define F_DIM   1024
#define KSEL    4
#define FRM_MAX 2048
#define C_MAX   100352          // 784 tiles of 128 >= ceil(100000/128)=782

// ---------------- mma tiling ----------------
#define MT      128             // queries per CTA tile
#define NT      128             // candidates per CTA tile
#define KC      64              // K elems per smem chunk (64 fp16 = 128B row)
#define NSLICE  19              // 16 x 19 = 304 CTAs = 2 waves
#define TILE_B  (128 * 128)     // 16KB per limb tile (128 rows x 128B)
#define NTILES  4               // per chunk: A0,A1,B0,B1
#define SMEM_DYN (2 * NTILES * TILE_B + 1024)
#define STAGE_PITCH 129         // f32 pitch for epilogue staging (conflict-free)

#define SWZ128(off) ((off) ^ (((off) >> 3) & 0x70))

// ---------------- device scratch (static: no allocations allowed) ----------------
__device__ float  g_invn[C_MAX];
__device__ __half g_qs[2][(size_t)FRM_MAX * F_DIM];   // Q fp16 limbs (8.4MB)
__device__ __half g_bs[2][(size_t)C_MAX * F_DIM];     // M fp16 limbs (411MB, tail 0)
__device__ float g_pv[(size_t)FRM_MAX * NSLICE * KSEL];
__device__ int   g_pi[(size_t)FRM_MAX * NSLICE * KSEL];

// ---------------- helpers ----------------
__device__ __forceinline__ uint32_t smem_u32(const void* p) {
    return (uint32_t)__cvta_generic_to_shared(p);
}
__device__ __forceinline__ void cp16(uint32_t dst, const void* src) {
    asm volatile("cp.async.cg.shared.global [%0], [%1], 16;" :: "r"(dst), "l"(src));
}
__device__ __forceinline__ void cp_commit() { asm volatile("cp.async.commit_group;" ::); }
__device__ __forceinline__ void cp_wait0()  { asm volatile("cp.async.wait_group 0;" ::: "memory"); }
__device__ __forceinline__ void cp_wait1()  { asm volatile("cp.async.wait_group 1;" ::: "memory"); }

__device__ __forceinline__ void ldmx4(uint32_t* r, uint32_t addr) {
    asm volatile("ldmatrix.sync.aligned.m8n8.x4.shared.b16 {%0,%1,%2,%3}, [%4];"
                 : "=r"(r[0]), "=r"(r[1]), "=r"(r[2]), "=r"(r[3]) : "r"(addr));
}
__device__ __forceinline__ void ldmx2(uint32_t* r, uint32_t addr) {
    asm volatile("ldmatrix.sync.aligned.m8n8.x2.shared.b16 {%0,%1}, [%2];"
                 : "=r"(r[0]), "=r"(r[1]) : "r"(addr));
}
__device__ __forceinline__ void mma_f16(float d[4], const uint32_t a[4], const uint32_t b[2]) {
    asm volatile("mma.sync.aligned.m16n8k16.row.col.f32.f16.f16.f32 "
                 "{%0,%1,%2,%3}, {%4,%5,%6,%7}, {%8,%9}, {%0,%1,%2,%3};"
                 : "+f"(d[0]), "+f"(d[1]), "+f"(d[2]), "+f"(d[3])
                 : "r"(a[0]), "r"(a[1]), "r"(a[2]), "r"(a[3]), "r"(b[0]), "r"(b[1]));
}

__device__ __forceinline__ void top4_insert(float s, int c, float v[KSEL], int ix[KSEL]) {
#pragma unroll
    for (int p = 0; p < KSEL; p++) {
        if (s > v[p]) {
#pragma unroll
            for (int q = KSEL - 1; q > p; q--) { v[q] = v[q - 1]; ix[q] = ix[q - 1]; }
            v[p] = s; ix[p] = c;
            break;
        }
    }
}

// ---------------- kernel 0: 2-limb fp16 split ----------------
__global__ void split_kernel(const float* __restrict__ X,
                             __half* __restrict__ d0,
                             __half* __restrict__ d1, size_t n4) {
    size_t i = (size_t)blockIdx.x * blockDim.x + threadIdx.x;
    if (i >= n4) return;
    float4 x = ((const float4*)X)[i];
    const float* xs = (const float*)&x;
    __half h0[4], h1[4];
#pragma unroll
    for (int j = 0; j < 4; j++) {
        float v = xs[j];
        __half a0 = __float2half_rn(v);
        float r1 = v - __half2float(a0);
        h0[j] = a0;
        h1[j] = __float2half_rn(r1);
    }
    __half2* p0 = (__half2*)d0 + i * 2;
    __half2* p1 = (__half2*)d1 + i * 2;
    __half2 t;
    t.x = h0[0]; t.y = h0[1]; p0[0] = t;  t.x = h0[2]; t.y = h0[3]; p0[1] = t;
    t.x = h1[0]; t.y = h1[1]; p1[0] = t;  t.x = h1[2]; t.y = h1[3]; p1[1] = t;
}

// ---------------- kernel 1: inverse norms ----------------
__global__ void norms_kernel(const float* __restrict__ M, int C) {
    int row  = blockIdx.x * 8 + (threadIdx.x >> 5);
    int lane = threadIdx.x & 31;
    if (row >= C) return;
    const float4* p = (const float4*)(M + (size_t)row * F_DIM);
    float s = 0.f;
#pragma unroll
    for (int i = 0; i < F_DIM / 4 / 32; i++) {
        float4 v = p[lane + i * 32];
        s += v.x * v.x + v.y * v.y + v.z * v.z + v.w * v.w;
    }
#pragma unroll
    for (int o = 16; o > 0; o >>= 1) s += __shfl_xor_sync(0xffffffffu, s, o);
    if (lane == 0) g_invn[row] = rsqrtf(s);
}

// ---------------- kernel 2: mma.sync fp16x3 GEMM + fused top-4 ----------------
__global__ void __launch_bounds__(256, 1)
knn_mma_kernel(int FRM, int C) {
    extern __shared__ __align__(16) char dsm[];
    __shared__ float sinv[NT];

    const int tid  = threadIdx.x;
    const int wid  = tid >> 5;
    const int lane = tid & 31;
    const int wr   = wid >> 2;        // warp row (0..1) -> 64 query rows
    const int wc   = wid & 3;         // warp col (0..3) -> 32 candidate cols
    const int mt   = blockIdx.x;
    const int sl   = blockIdx.y;

    const uint32_t dsm_u    = smem_u32(dsm);
    const uint32_t tilebase = (dsm_u + 1023u) & ~1023u;
    float* stagef = (float*)(dsm + (tilebase - dsm_u));   // epilogue staging reuses tiles

    const int tiles_total = (C + NT - 1) / NT;
    const int t0 = (int)((long long)sl       * tiles_total / NSLICE);
    const int t1 = (int)((long long)(sl + 1) * tiles_total / NSLICE);

    const int a_row = lane & 15;            // A: row within m16 tile
    const int a_sel = lane >> 4;            // A: k-half
    const int b_row = lane & 7;             // B: row within n8 tile
    const int b_sel = (lane >> 3) & 1;      // B: k-half

    float tv[KSEL]; int ti[KSEL];
#pragma unroll
    for (int p = 0; p < KSEL; p++) { tv[p] = -3.4e38f; ti[p] = 0; }

    for (int ct = t0; ct < t1; ct++) {
        const int c0 = ct * NT;

        // ---- load one K-chunk slab (4 limb tiles, 64KB) into buffer `buf` ----
        auto load_slab = [&](int kc, int buf) {
            const uint32_t bb = tilebase + (uint32_t)(buf * NTILES) * TILE_B;
#pragma unroll
            for (int t = 0; t < 16; t++) {
                int idx   = tid + t * 256;        // 0..4095
                int tile  = idx >> 10;            // 0-1: A limbs, 2-3: B limbs
                int ch    = idx & 1023;
                int row   = ch >> 3;              // 0..127
                int col16 = ch & 7;               // 16B unit in 128B row
                uint32_t dst = bb + (uint32_t)tile * TILE_B
                             + SWZ128((uint32_t)(row * 128 + col16 * 16));
                const __half* src;
                if (tile < 2) {
                    int qr = mt * MT + row; if (qr >= FRM) qr = FRM - 1;
                    src = &g_qs[tile][(size_t)qr * F_DIM + kc * KC + col16 * 8];
                } else {
                    src = &g_bs[tile - 2][(size_t)(c0 + row) * F_DIM + kc * KC + col16 * 8];
                }
                cp16(dst, src);
            }
            cp_commit();
        };

        float acc[4][4][4];
#pragma unroll
        for (int mi = 0; mi < 4; mi++)
#pragma unroll
            for (int ni = 0; ni < 4; ni++)
#pragma unroll
                for (int r = 0; r < 4; r++) acc[mi][ni][r] = 0.f;

        load_slab(0, 0);

        const int NKC = F_DIM / KC;   // 16
        for (int kc = 0; kc < NKC; kc++) {
            const int buf = kc & 1;
            const bool more = (kc + 1 < NKC);
            if (more) { load_slab(kc + 1, buf ^ 1); cp_wait1(); }
            else      { cp_wait0(); }
            __syncthreads();           // slab `buf` visible to all warps

            const uint32_t bb = tilebase + (uint32_t)(buf * NTILES) * TILE_B;
            const uint32_t A0 = bb;
            const uint32_t A1 = bb + TILE_B;
            const uint32_t B0 = bb + 2 * TILE_B;
            const uint32_t B1 = bb + 3 * TILE_B;

#pragma unroll
            for (int ks = 0; ks < 4; ks++) {          // 4 x k16 per 64-chunk
                // hoisted fragment loads: each limb loaded ONCE per k-step
                uint32_t af[2][4][4];
                uint32_t bf[2][4][2];
#pragma unroll
                for (int mi = 0; mi < 4; mi++) {
                    int row = wr * 64 + mi * 16 + a_row;
                    uint32_t off = SWZ128((uint32_t)(row * 128 + (ks * 2 + a_sel) * 16));
                    ldmx4(af[0][mi], A0 + off);
                    ldmx4(af[1][mi], A1 + off);
                }
#pragma unroll
                for (int ni = 0; ni < 4; ni++) {
                    int row = wc * 32 + ni * 8 + b_row;
                    uint32_t off = SWZ128((uint32_t)(row * 128 + (ks * 2 + b_sel) * 16));
                    ldmx2(bf[0][ni], B0 + off);
                    ldmx2(bf[1][ni], B1 + off);
                }
                // 3 limb products: 00, 01, 10  (11 ~ residual scale, dropped)
#pragma unroll
                for (int mi = 0; mi < 4; mi++)
#pragma unroll
                    for (int ni = 0; ni < 4; ni++) {
                        mma_f16(acc[mi][ni], af[0][mi], bf[0][ni]);
                        mma_f16(acc[mi][ni], af[0][mi], bf[1][ni]);
                        mma_f16(acc[mi][ni], af[1][mi], bf[0][ni]);
                    }
            }
            __syncthreads();           // all reads of `buf` done before refill
        }

        // ---- epilogue: stage D in smem (pitch 129), scan rows, update top-4 ----
        if (tid < NT) sinv[tid] = g_invn[c0 + tid];
#pragma unroll
        for (int mi = 0; mi < 4; mi++) {
            int R0 = wr * 64 + mi * 16 + (lane >> 2);
#pragma unroll
            for (int ni = 0; ni < 4; ni++) {
                int Cc = wc * 32 + ni * 8 + 2 * (lane & 3);
                stagef[R0 * STAGE_PITCH + Cc]           = acc[mi][ni][0];
                stagef[R0 * STAGE_PITCH + Cc + 1]       = acc[mi][ni][1];
                stagef[(R0 + 8) * STAGE_PITCH + Cc]     = acc[mi][ni][2];
                stagef[(R0 + 8) * STAGE_PITCH + Cc + 1] = acc[mi][ni][3];
            }
        }
        __syncthreads();

        if (tid < MT) {
            const float* rowp = stagef + tid * STAGE_PITCH;
#pragma unroll 4
            for (int j = 0; j < NT; j++) {
                int gc = c0 + j;
                if (gc < C) top4_insert(rowp[j] * sinv[j], gc, tv, ti);
            }
        }
        __syncthreads();   // staging fully read before next tile's loads overwrite it
    }

    // ---- write per-(query, slice) top-4 partials ----
    const int q = mt * MT + tid;
    if (tid < MT && q < FRM) {
        size_t base = ((size_t)q * NSLICE + sl) * KSEL;
#pragma unroll
        for (int p = 0; p < KSEL; p++) { g_pv[base + p] = tv[p]; g_pi[base + p] = ti[p]; }
    }
}

// ---------------- kernel 3: merge partials, gather synth rows, average ----------------
__global__ void merge_gather_kernel(const float* __restrict__ S, float* __restrict__ out,
                                    int FRM, int C) {
    __shared__ float sv[32 * KSEL];
    __shared__ int   si[32 * KSEL];
    __shared__ int   fidx[KSEL];

    const int q   = blockIdx.x;
    const int tid = threadIdx.x;
    const int E   = NSLICE * KSEL;   // 76 partial entries per query

    if (tid < 32) {
        float v[KSEL]; int ix[KSEL];
#pragma unroll
        for (int p = 0; p < KSEL; p++) { v[p] = -3.4e38f; ix[p] = 0; }
        const size_t base = (size_t)q * E;
        for (int e = tid; e < E; e += 32)
            top4_insert(g_pv[base + e], g_pi[base + e], v, ix);
#pragma unroll
        for (int p = 0; p < KSEL; p++) { sv[tid * KSEL + p] = v[p]; si[tid * KSEL + p] = ix[p]; }
    }
    __syncthreads();
    if (tid == 0) {
        float v[KSEL]; int ix[KSEL];
#pragma unroll
        for (int p = 0; p < KSEL; p++) { v[p] = -3.4e38f; ix[p] = 0; }
        for (int e = 0; e < 32 * KSEL; e++) top4_insert(sv[e], si[e], v, ix);
#pragma unroll
        for (int p = 0; p < KSEL; p++) fidx[p] = ix[p];
    }
    __syncthreads();

    const float4* s0 = (const float4*)(S + (size_t)fidx[0] * F_DIM);
    const float4* s1 = (const float4*)(S + (size_t)fidx[1] * F_DIM);
    const float4* s2 = (const float4*)(S + (size_t)fidx[2] * F_DIM);
    const float4* s3 = (const float4*)(S + (size_t)fidx[3] * F_DIM);
    float4* o = (float4*)(out + (size_t)q * F_DIM);

    for (int pos = tid; pos < F_DIM / 4; pos += blockDim.x) {
        float4 a = s0[pos], b = s1[pos], c = s2[pos], d = s3[pos];
        float4 r;
        r.x = (a.x + b.x + c.x + d.x) * 0.25f;
        r.y = (a.y + b.y + c.y + d.y) * 0.25f;
        r.z = (a.z + b.z + c.z + d.z) * 0.25f;
        r.w = (a.w + b.w + c.w + d.w) * 0.25f;
        o[pos] = r;
    }
}

// ---------------- launch ----------------
extern "C" void kernel_launch(void* const* d_in, const int* in_sizes, int n_in,
                              void* d_out, int out_size) {
    const float* Q = (const float*)d_in[0];   // query_seq    (FRM, F)
    const float* M = (const float*)d_in[1];   // matching_set (C, F)
    const float* S = (const float*)d_in[2];   // synth_set    (C, F)
    float* out = (float*)d_out;

    const int FRM = in_sizes[0] / F_DIM;
    const int C   = in_sizes[1] / F_DIM;

    cudaFuncSetAttribute(knn_mma_kernel, cudaFuncAttributeMaxDynamicSharedMemorySize, SMEM_DYN);

    norms_kernel<<<(C + 7) / 8, 256>>>(M, C);

    __half *q0, *b0;
    cudaGetSymbolAddress((void**)&q0, g_qs);
    cudaGetSymbolAddress((void**)&b0, g_bs);
    __half *q1 = q0 + (size_t)FRM_MAX * F_DIM;
    __half *b1 = b0 + (size_t)C_MAX * F_DIM;

    size_t nm4 = (size_t)C * F_DIM / 4;
    size_t nq4 = (size_t)FRM * F_DIM / 4;
    split_kernel<<<(unsigned)((nm4 + 255) / 256), 256>>>(M, b0, b1, nm4);
    split_kernel<<<(unsigned)((nq4 + 255) / 256), 256>>>(Q, q0, q1, nq4);

    dim3 g2((FRM + MT - 1) / MT, NSLICE);
    knn_mma_kernel<<<g2, 256, SMEM_DYN>>>(FRM, C);

    merge_gather_kernel<<<FRM, 256>>>(S, out, FRM, C);
}

// round 15
// speedup vs baseline: 3.5960x; 1.0953x over previous
#include <cuda_runtime.h>
#include <cuda_fp16.h>
#include <cstdint>

// ---------------- problem constants ----------------
#define F_DIM   1024
#define KSEL    4
#define FRM_MAX 2048
#define C_MAX   100352          // 784 tiles of 128 >= ceil(100000/128)=782

// ---------------- mma tiling ----------------
#define MT      128             // queries per CTA tile
#define NT      128             // candidates per CTA tile
#define KC      64              // K elems per smem chunk (64 fp16 = 128B row)
#define NSLICE  19              // 16 x 19 = 304 CTAs = 2 waves
#define TILE_B  (128 * 128)     // 16KB per limb tile (128 rows x 128B)
#define NTILES  4               // per chunk: A0,A1,B0,B1
#define SMEM_DYN (2 * NTILES * TILE_B + 1024)
#define STAGE_PITCH 129         // f32 pitch for epilogue staging
#define NTHREADS 512            // 16 warps -> 4 per SMSP

#define SWZ128(off) ((off) ^ (((off) >> 3) & 0x70))

// ---------------- device scratch (static: no allocations allowed) ----------------
__device__ float  g_invn[C_MAX];
__device__ __half g_qs[2][(size_t)FRM_MAX * F_DIM];   // Q fp16 limbs
__device__ __half g_bs[2][(size_t)C_MAX * F_DIM];     // M fp16 limbs (tail rows 0)
__device__ float g_pv[(size_t)FRM_MAX * NSLICE * 2 * KSEL];  // 2 col-halves per slice
__device__ int   g_pi[(size_t)FRM_MAX * NSLICE * 2 * KSEL];

// ---------------- helpers ----------------
__device__ __forceinline__ uint32_t smem_u32(const void* p) {
    return (uint32_t)__cvta_generic_to_shared(p);
}
__device__ __forceinline__ void cp16(uint32_t dst, const void* src) {
    asm volatile("cp.async.cg.shared.global [%0], [%1], 16;" :: "r"(dst), "l"(src));
}
__device__ __forceinline__ void cp_commit() { asm volatile("cp.async.commit_group;" ::); }
__device__ __forceinline__ void cp_wait0()  { asm volatile("cp.async.wait_group 0;" ::: "memory"); }
__device__ __forceinline__ void cp_wait1()  { asm volatile("cp.async.wait_group 1;" ::: "memory"); }

__device__ __forceinline__ void ldmx4(uint32_t* r, uint32_t addr) {
    asm volatile("ldmatrix.sync.aligned.m8n8.x4.shared.b16 {%0,%1,%2,%3}, [%4];"
                 : "=r"(r[0]), "=r"(r[1]), "=r"(r[2]), "=r"(r[3]) : "r"(addr));
}
__device__ __forceinline__ void mma_f16(float d[4], const uint32_t a[4], const uint32_t b[2]) {
    asm volatile("mma.sync.aligned.m16n8k16.row.col.f32.f16.f16.f32 "
                 "{%0,%1,%2,%3}, {%4,%5,%6,%7}, {%8,%9}, {%0,%1,%2,%3};"
                 : "+f"(d[0]), "+f"(d[1]), "+f"(d[2]), "+f"(d[3])
                 : "r"(a[0]), "r"(a[1]), "r"(a[2]), "r"(a[3]), "r"(b[0]), "r"(b[1]));
}

__device__ __forceinline__ void top4_insert(float s, int c, float v[KSEL], int ix[KSEL]) {
#pragma unroll
    for (int p = 0; p < KSEL; p++) {
        if (s > v[p]) {
#pragma unroll
            for (int q = KSEL - 1; q > p; q--) { v[q] = v[q - 1]; ix[q] = ix[q - 1]; }
            v[p] = s; ix[p] = c;
            break;
        }
    }
}

// ---------------- kernel 0: 2-limb fp16 split ----------------
__global__ void split_kernel(const float* __restrict__ X,
                             __half* __restrict__ d0,
                             __half* __restrict__ d1, size_t n4) {
    size_t i = (size_t)blockIdx.x * blockDim.x + threadIdx.x;
    if (i >= n4) return;
    float4 x = ((const float4*)X)[i];
    const float* xs = (const float*)&x;
    __half h0[4], h1[4];
#pragma unroll
    for (int j = 0; j < 4; j++) {
        float v = xs[j];
        __half a0 = __float2half_rn(v);
        float r1 = v - __half2float(a0);
        h0[j] = a0;
        h1[j] = __float2half_rn(r1);
    }
    __half2* p0 = (__half2*)d0 + i * 2;
    __half2* p1 = (__half2*)d1 + i * 2;
    __half2 t;
    t.x = h0[0]; t.y = h0[1]; p0[0] = t;  t.x = h0[2]; t.y = h0[3]; p0[1] = t;
    t.x = h1[0]; t.y = h1[1]; p1[0] = t;  t.x = h1[2]; t.y = h1[3]; p1[1] = t;
}

// ---------------- kernel 1: inverse norms ----------------
__global__ void norms_kernel(const float* __restrict__ M, int C) {
    int row  = blockIdx.x * 8 + (threadIdx.x >> 5);
    int lane = threadIdx.x & 31;
    if (row >= C) return;
    const float4* p = (const float4*)(M + (size_t)row * F_DIM);
    float s = 0.f;
#pragma unroll
    for (int i = 0; i < F_DIM / 4 / 32; i++) {
        float4 v = p[lane + i * 32];
        s += v.x * v.x + v.y * v.y + v.z * v.z + v.w * v.w;
    }
#pragma unroll
    for (int o = 16; o > 0; o >>= 1) s += __shfl_xor_sync(0xffffffffu, s, o);
    if (lane == 0) g_invn[row] = rsqrtf(s);
}

// ---------------- kernel 2: mma.sync fp16x3 GEMM, 16 warps, fused top-4 ----------------
__global__ void __launch_bounds__(NTHREADS, 1)
knn_mma_kernel(int FRM, int C) {
    extern __shared__ __align__(16) char dsm[];
    __shared__ float sinv[NT];

    const int tid  = threadIdx.x;
    const int wid  = tid >> 5;
    const int lane = tid & 31;
    const int wr   = wid >> 2;        // warp row (0..3) -> 32 query rows
    const int wc   = wid & 3;         // warp col (0..3) -> 32 candidate cols
    const int mt   = blockIdx.x;
    const int sl   = blockIdx.y;

    const uint32_t dsm_u    = smem_u32(dsm);
    const uint32_t tilebase = (dsm_u + 1023u) & ~1023u;
    float* stagef = (float*)(dsm + (tilebase - dsm_u));   // epilogue staging reuses tiles

    const int tiles_total = (C + NT - 1) / NT;
    const int t0 = (int)((long long)sl       * tiles_total / NSLICE);
    const int t1 = (int)((long long)(sl + 1) * tiles_total / NSLICE);

    // ldmatrix lane address components
    const int a_row = lane & 15;            // A: row within m16 tile (lanes 0-15)
    const int a_sel = lane >> 4;            // A: k-half unit
    const int b_g   = lane >> 3;            // B x4: lane group 0-3
    const int b_row = lane & 7;             // B: row within n8 tile

    // running top-4: threads 0-255 own (query row tid&127, col-half tid>>7)
    float tv[KSEL]; int ti[KSEL];
#pragma unroll
    for (int p = 0; p < KSEL; p++) { tv[p] = -3.4e38f; ti[p] = 0; }

    for (int ct = t0; ct < t1; ct++) {
        const int c0 = ct * NT;

        // ---- load one K-chunk slab (4 limb tiles, 64KB) into buffer `buf` ----
        auto load_slab = [&](int kc, int buf) {
            const uint32_t bb = tilebase + (uint32_t)(buf * NTILES) * TILE_B;
#pragma unroll
            for (int t = 0; t < 8; t++) {
                int idx   = tid + t * NTHREADS;   // 0..4095
                int tile  = idx >> 10;            // 0-1: A limbs, 2-3: B limbs
                int ch    = idx & 1023;
                int row   = ch >> 3;              // 0..127
                int col16 = ch & 7;               // 16B unit in 128B row
                uint32_t dst = bb + (uint32_t)tile * TILE_B
                             + SWZ128((uint32_t)(row * 128 + col16 * 16));
                const __half* src;
                if (tile < 2) {
                    int qr = mt * MT + row; if (qr >= FRM) qr = FRM - 1;
                    src = &g_qs[tile][(size_t)qr * F_DIM + kc * KC + col16 * 8];
                } else {
                    src = &g_bs[tile - 2][(size_t)(c0 + row) * F_DIM + kc * KC + col16 * 8];
                }
                cp16(dst, src);
            }
            cp_commit();
        };

        // accumulators: 2 m16 x 4 n8 per warp (32x32 warp tile)
        float acc[2][4][4];
#pragma unroll
        for (int mi = 0; mi < 2; mi++)
#pragma unroll
            for (int ni = 0; ni < 4; ni++)
#pragma unroll
                for (int r = 0; r < 4; r++) acc[mi][ni][r] = 0.f;

        load_slab(0, 0);

        const int NKC = F_DIM / KC;   // 16
        for (int kc = 0; kc < NKC; kc++) {
            const int buf = kc & 1;
            const bool more = (kc + 1 < NKC);
            if (more) { load_slab(kc + 1, buf ^ 1); cp_wait1(); }
            else      { cp_wait0(); }
            __syncthreads();           // slab `buf` visible to all warps

            const uint32_t bb = tilebase + (uint32_t)(buf * NTILES) * TILE_B;
            const uint32_t A0 = bb;
            const uint32_t A1 = bb + TILE_B;
            const uint32_t B0 = bb + 2 * TILE_B;
            const uint32_t B1 = bb + 3 * TILE_B;

#pragma unroll
            for (int ks = 0; ks < 4; ks++) {          // 4 x k16 per 64-chunk
                uint32_t af[2][2][4];   // [limb][mi]
                uint32_t bf[2][4][2];   // [limb][ni]
#pragma unroll
                for (int mi = 0; mi < 2; mi++) {
                    int row = wr * 32 + mi * 16 + a_row;
                    uint32_t off = SWZ128((uint32_t)(row * 128 + (ks * 2 + a_sel) * 16));
                    ldmx4(af[0][mi], A0 + off);
                    ldmx4(af[1][mi], A1 + off);
                }
                // B via x4: matrices (nb,k0),(nb,k1),(nb+1,k0),(nb+1,k1)
#pragma unroll
                for (int nb = 0; nb < 4; nb += 2) {
                    int row = wc * 32 + (nb + (b_g >> 1)) * 8 + b_row;
                    uint32_t off = SWZ128((uint32_t)(row * 128 + (ks * 2 + (b_g & 1)) * 16));
                    uint32_t r4[4];
                    ldmx4(r4, B0 + off);
                    bf[0][nb][0] = r4[0]; bf[0][nb][1] = r4[1];
                    bf[0][nb + 1][0] = r4[2]; bf[0][nb + 1][1] = r4[3];
                    ldmx4(r4, B1 + off);
                    bf[1][nb][0] = r4[0]; bf[1][nb][1] = r4[1];
                    bf[1][nb + 1][0] = r4[2]; bf[1][nb + 1][1] = r4[3];
                }
                // 3 limb products: 00, 01, 10
#pragma unroll
                for (int mi = 0; mi < 2; mi++)
#pragma unroll
                    for (int ni = 0; ni < 4; ni++) {
                        mma_f16(acc[mi][ni], af[0][mi], bf[0][ni]);
                        mma_f16(acc[mi][ni], af[0][mi], bf[1][ni]);
                        mma_f16(acc[mi][ni], af[1][mi], bf[0][ni]);
                    }
            }
            __syncthreads();           // all reads of `buf` done before refill
        }

        // ---- epilogue: stage D in smem (pitch 129), 2x-parallel scan, top-4 ----
        if (tid < NT) sinv[tid] = g_invn[c0 + tid];
#pragma unroll
        for (int mi = 0; mi < 2; mi++) {
            int R0 = wr * 32 + mi * 16 + (lane >> 2);
#pragma unroll
            for (int ni = 0; ni < 4; ni++) {
                int Cc = wc * 32 + ni * 8 + 2 * (lane & 3);
                stagef[R0 * STAGE_PITCH + Cc]           = acc[mi][ni][0];
                stagef[R0 * STAGE_PITCH + Cc + 1]       = acc[mi][ni][1];
                stagef[(R0 + 8) * STAGE_PITCH + Cc]     = acc[mi][ni][2];
                stagef[(R0 + 8) * STAGE_PITCH + Cc + 1] = acc[mi][ni][3];
            }
        }
        __syncthreads();

        if (tid < 2 * MT) {
            const int row = tid & 127;
            const int ch  = tid >> 7;            // col half 0/1
            const float* rowp = stagef + row * STAGE_PITCH + ch * 64;
            const float* sp   = sinv + ch * 64;
#pragma unroll 4
            for (int j = 0; j < 64; j++) {
                int gc = c0 + ch * 64 + j;
                if (gc < C) top4_insert(rowp[j] * sp[j], gc, tv, ti);
            }
        }
        __syncthreads();   // staging fully read before next tile's loads overwrite it
    }

    // ---- write per-(query, slice, col-half) top-4 partials ----
    if (tid < 2 * MT) {
        const int row = tid & 127;
        const int ch  = tid >> 7;
        const int q   = mt * MT + row;
        if (q < FRM) {
            size_t base = (((size_t)q * NSLICE + sl) * 2 + ch) * KSEL;
#pragma unroll
            for (int p = 0; p < KSEL; p++) { g_pv[base + p] = tv[p]; g_pi[base + p] = ti[p]; }
        }
    }
}

// ---------------- kernel 3: merge partials, gather synth rows, average ----------------
__global__ void merge_gather_kernel(const float* __restrict__ S, float* __restrict__ out,
                                    int FRM, int C) {
    __shared__ float sv[32 * KSEL];
    __shared__ int   si[32 * KSEL];
    __shared__ int   fidx[KSEL];

    const int q   = blockIdx.x;
    const int tid = threadIdx.x;
    const int E   = NSLICE * 2 * KSEL;   // 152 partial entries per query

    if (tid < 32) {
        float v[KSEL]; int ix[KSEL];
#pragma unroll
        for (int p = 0; p < KSEL; p++) { v[p] = -3.4e38f; ix[p] = 0; }
        const size_t base = (size_t)q * E;
        for (int e = tid; e < E; e += 32)
            top4_insert(g_pv[base + e], g_pi[base + e], v, ix);
#pragma unroll
        for (int p = 0; p < KSEL; p++) { sv[tid * KSEL + p] = v[p]; si[tid * KSEL + p] = ix[p]; }
    }
    __syncthreads();
    if (tid == 0) {
        float v[KSEL]; int ix[KSEL];
#pragma unroll
        for (int p = 0; p < KSEL; p++) { v[p] = -3.4e38f; ix[p] = 0; }
        for (int e = 0; e < 32 * KSEL; e++) top4_insert(sv[e], si[e], v, ix);
#pragma unroll
        for (int p = 0; p < KSEL; p++) fidx[p] = ix[p];
    }
    __syncthreads();

    const float4* s0 = (const float4*)(S + (size_t)fidx[0] * F_DIM);
    const float4* s1 = (const float4*)(S + (size_t)fidx[1] * F_DIM);
    const float4* s2 = (const float4*)(S + (size_t)fidx[2] * F_DIM);
    const float4* s3 = (const float4*)(S + (size_t)fidx[3] * F_DIM);
    float4* o = (float4*)(out + (size_t)q * F_DIM);

    for (int pos = tid; pos < F_DIM / 4; pos += blockDim.x) {
        float4 a = s0[pos], b = s1[pos], c = s2[pos], d = s3[pos];
        float4 r;
        r.x = (a.x + b.x + c.x + d.x) * 0.25f;
        r.y = (a.y + b.y + c.y + d.y) * 0.25f;
        r.z = (a.z + b.z + c.z + d.z) * 0.25f;
        r.w = (a.w + b.w + c.w + d.w) * 0.25f;
        o[pos] = r;
    }
}

// ---------------- launch ----------------
extern "C" void kernel_launch(void* const* d_in, const int* in_sizes, int n_in,
                              void* d_out, int out_size) {
    const float* Q = (const float*)d_in[0];   // query_seq    (FRM, F)
    const float* M = (const float*)d_in[1];   // matching_set (C, F)
    const float* S = (const float*)d_in[2];   // synth_set    (C, F)
    float* out = (float*)d_out;

    const int FRM = in_sizes[0] / F_DIM;
    const int C   = in_sizes[1] / F_DIM;

    cudaFuncSetAttribute(knn_mma_kernel, cudaFuncAttributeMaxDynamicSharedMemorySize, SMEM_DYN);

    norms_kernel<<<(C + 7) / 8, 256>>>(M, C);

    __half *q0, *b0;
    cudaGetSymbolAddress((void**)&q0, g_qs);
    cudaGetSymbolAddress((void**)&b0, g_bs);
    __half *q1 = q0 + (size_t)FRM_MAX * F_DIM;
    __half *b1 = b0 + (size_t)C_MAX * F_DIM;

    size_t nm4 = (size_t)C * F_DIM / 4;
    size_t nq4 = (size_t)FRM * F_DIM / 4;
    split_kernel<<<(unsigned)((nm4 + 255) / 256), 256>>>(M, b0, b1, nm4);
    split_kernel<<<(unsigned)((nq4 + 255) / 256), 256>>>(Q, q0, q1, nq4);

    dim3 g2((FRM + MT - 1) / MT, NSLICE);
    knn_mma_kernel<<<g2, NTHREADS, SMEM_DYN>>>(FRM, C);

    merge_gather_kernel<<<FRM, 256>>>(S, out, FRM, C);
}

// round 16
// speedup vs baseline: 3.9991x; 1.1121x over previous
#include <cuda_runtime.h>
#include <cuda_fp16.h>
#include <cstdint>

// ---------------- problem constants ----------------
#define F_DIM   1024
#define KSEL    4
#define FRM_MAX 2048
#define C_MAX   100352

// ---------------- mma tiling ----------------
#define MT      128             // queries per CTA tile
#define NT      64              // candidates per CTA tile (half: 2 CTAs/SM)
#define KC      64              // K elems per smem chunk (64 fp16 = 128B row)
#define NSLICE  38              // 16 x 38 = 608 CTAs = 2 waves at 2 CTA/SM
#define A_T_B   (128 * 128)     // 16KB per A limb tile
#define B_T_B   (64 * 128)      // 8KB per B limb tile
#define STAGE_B (2 * A_T_B + 2 * B_T_B)   // 48KB per pipeline stage
#define SMEM_DYN (2 * STAGE_B + 1024)
#define STAGE_PITCH 65          // f32 pitch for 128x64 epilogue staging
#define NTHREADS 256            // 8 warps; 2 CTAs/SM -> 4 warps/SMSP

#define SWZ128(off) ((off) ^ (((off) >> 3) & 0x70))

// ---------------- device scratch (static: no allocations allowed) ----------------
__device__ float  g_invn[C_MAX];
__device__ __half g_qs[2][(size_t)FRM_MAX * F_DIM];   // Q fp16 limbs
__device__ __half g_bs[2][(size_t)C_MAX * F_DIM];     // M fp16 limbs (tail rows 0)
__device__ float g_pv[(size_t)FRM_MAX * NSLICE * 2 * KSEL];  // 2 col-halves/slice
__device__ int   g_pi[(size_t)FRM_MAX * NSLICE * 2 * KSEL];

// ---------------- helpers ----------------
__device__ __forceinline__ uint32_t smem_u32(const void* p) {
    return (uint32_t)__cvta_generic_to_shared(p);
}
__device__ __forceinline__ void cp16(uint32_t dst, const void* src) {
    asm volatile("cp.async.cg.shared.global [%0], [%1], 16;" :: "r"(dst), "l"(src));
}
__device__ __forceinline__ void cp_commit() { asm volatile("cp.async.commit_group;" ::); }
__device__ __forceinline__ void cp_wait0()  { asm volatile("cp.async.wait_group 0;" ::: "memory"); }
__device__ __forceinline__ void cp_wait1()  { asm volatile("cp.async.wait_group 1;" ::: "memory"); }

__device__ __forceinline__ void ldmx4(uint32_t* r, uint32_t addr) {
    asm volatile("ldmatrix.sync.aligned.m8n8.x4.shared.b16 {%0,%1,%2,%3}, [%4];"
                 : "=r"(r[0]), "=r"(r[1]), "=r"(r[2]), "=r"(r[3]) : "r"(addr));
}
__device__ __forceinline__ void mma_f16(float d[4], const uint32_t a[4], const uint32_t b[2]) {
    asm volatile("mma.sync.aligned.m16n8k16.row.col.f32.f16.f16.f32 "
                 "{%0,%1,%2,%3}, {%4,%5,%6,%7}, {%8,%9}, {%0,%1,%2,%3};"
                 : "+f"(d[0]), "+f"(d[1]), "+f"(d[2]), "+f"(d[3])
                 : "r"(a[0]), "r"(a[1]), "r"(a[2]), "r"(a[3]), "r"(b[0]), "r"(b[1]));
}

__device__ __forceinline__ void top4_insert(float s, int c, float v[KSEL], int ix[KSEL]) {
#pragma unroll
    for (int p = 0; p < KSEL; p++) {
        if (s > v[p]) {
#pragma unroll
            for (int q = KSEL - 1; q > p; q--) { v[q] = v[q - 1]; ix[q] = ix[q - 1]; }
            v[p] = s; ix[p] = c;
            break;
        }
    }
}

// ---------------- kernel 0: 2-limb fp16 split ----------------
__global__ void split_kernel(const float* __restrict__ X,
                             __half* __restrict__ d0,
                             __half* __restrict__ d1, size_t n4) {
    size_t i = (size_t)blockIdx.x * blockDim.x + threadIdx.x;
    if (i >= n4) return;
    float4 x = ((const float4*)X)[i];
    const float* xs = (const float*)&x;
    __half h0[4], h1[4];
#pragma unroll
    for (int j = 0; j < 4; j++) {
        float v = xs[j];
        __half a0 = __float2half_rn(v);
        float r1 = v - __half2float(a0);
        h0[j] = a0;
        h1[j] = __float2half_rn(r1);
    }
    __half2* p0 = (__half2*)d0 + i * 2;
    __half2* p1 = (__half2*)d1 + i * 2;
    __half2 t;
    t.x = h0[0]; t.y = h0[1]; p0[0] = t;  t.x = h0[2]; t.y = h0[3]; p0[1] = t;
    t.x = h1[0]; t.y = h1[1]; p1[0] = t;  t.x = h1[2]; t.y = h1[3]; p1[1] = t;
}

// ---------------- kernel 1: inverse norms ----------------
__global__ void norms_kernel(const float* __restrict__ M, int C) {
    int row  = blockIdx.x * 8 + (threadIdx.x >> 5);
    int lane = threadIdx.x & 31;
    if (row >= C) return;
    const float4* p = (const float4*)(M + (size_t)row * F_DIM);
    float s = 0.f;
#pragma unroll
    for (int i = 0; i < F_DIM / 4 / 32; i++) {
        float4 v = p[lane + i * 32];
        s += v.x * v.x + v.y * v.y + v.z * v.z + v.w * v.w;
    }
#pragma unroll
    for (int o = 16; o > 0; o >>= 1) s += __shfl_xor_sync(0xffffffffu, s, o);
    if (lane == 0) g_invn[row] = rsqrtf(s);
}

// ---------------- kernel 2: mma.sync fp16x3 GEMM, 2 CTAs/SM, fused top-4 ----------------
__global__ void __launch_bounds__(NTHREADS, 2)
knn_mma_kernel(int FRM, int C) {
    extern __shared__ __align__(16) char dsm[];
    __shared__ float sinv[NT];

    const int tid  = threadIdx.x;
    const int wid  = tid >> 5;
    const int lane = tid & 31;
    const int wr   = wid >> 1;        // warp row (0..3) -> 32 query rows
    const int wc   = wid & 1;         // warp col (0..1) -> 32 candidate cols
    const int mt   = blockIdx.x;
    const int sl   = blockIdx.y;

    const uint32_t dsm_u    = smem_u32(dsm);
    const uint32_t tilebase = (dsm_u + 1023u) & ~1023u;
    float* stagef = (float*)(dsm + (tilebase - dsm_u));   // epilogue staging reuses stage 0

    const int tiles_total = (C + NT - 1) / NT;
    const int t0 = (int)((long long)sl       * tiles_total / NSLICE);
    const int t1 = (int)((long long)(sl + 1) * tiles_total / NSLICE);

    // ldmatrix lane address components
    const int a_row = lane & 15;            // A: row within m16 tile
    const int a_sel = lane >> 4;            // A: k-half unit
    const int b_g   = lane >> 3;            // B x4: lane group 0-3
    const int b_row = lane & 7;             // B: row within n8 tile

    // per-thread loader coords (hoisted)
    const int l_row8 = tid >> 3;            // 0..31
    const int l_c16  = tid & 7;

    // running top-4: thread owns (query row tid&127, col-half tid>>7)
    float tv[KSEL]; int ti[KSEL];
#pragma unroll
    for (int p = 0; p < KSEL; p++) { tv[p] = -3.4e38f; ti[p] = 0; }

    for (int ct = t0; ct < t1; ct++) {
        const int c0 = ct * NT;

        // ---- load one K-chunk slab (48KB: A0,A1,B0,B1) into buffer `buf` ----
        auto load_slab = [&](int kc, int buf) {
            const uint32_t bb = tilebase + (uint32_t)buf * STAGE_B;
            // A limbs: t=0..7 (tile t>>2, rows l_row8 + (t&3)*32)
#pragma unroll
            for (int t = 0; t < 8; t++) {
                int tile = t >> 2;
                int row  = l_row8 + (t & 3) * 32;
                uint32_t dst = bb + (uint32_t)tile * A_T_B
                             + SWZ128((uint32_t)(row * 128 + l_c16 * 16));
                int qr = mt * MT + row; if (qr >= FRM) qr = FRM - 1;
                cp16(dst, &g_qs[tile][(size_t)qr * F_DIM + kc * KC + l_c16 * 8]);
            }
            // B limbs: t=0..3 (tile t>>1, rows l_row8 + (t&1)*32)
#pragma unroll
            for (int t = 0; t < 4; t++) {
                int tile = t >> 1;
                int row  = l_row8 + (t & 1) * 32;
                uint32_t dst = bb + 2 * A_T_B + (uint32_t)tile * B_T_B
                             + SWZ128((uint32_t)(row * 128 + l_c16 * 16));
                cp16(dst, &g_bs[tile][(size_t)(c0 + row) * F_DIM + kc * KC + l_c16 * 8]);
            }
            cp_commit();
        };

        // accumulators: 2 m16 x 4 n8 per warp (32x32 warp tile)
        float acc[2][4][4];
#pragma unroll
        for (int mi = 0; mi < 2; mi++)
#pragma unroll
            for (int ni = 0; ni < 4; ni++)
#pragma unroll
                for (int r = 0; r < 4; r++) acc[mi][ni][r] = 0.f;

        load_slab(0, 0);

        const int NKC = F_DIM / KC;   // 16
        for (int kc = 0; kc < NKC; kc++) {
            const int buf = kc & 1;
            const bool more = (kc + 1 < NKC);
            if (more) { load_slab(kc + 1, buf ^ 1); cp_wait1(); }
            else      { cp_wait0(); }
            __syncthreads();           // slab `buf` visible to all warps

            const uint32_t bb = tilebase + (uint32_t)buf * STAGE_B;
            const uint32_t A0 = bb;
            const uint32_t A1 = bb + A_T_B;
            const uint32_t B0 = bb + 2 * A_T_B;
            const uint32_t B1 = bb + 2 * A_T_B + B_T_B;

#pragma unroll
            for (int ks = 0; ks < 4; ks++) {          // 4 x k16 per 64-chunk
                uint32_t af[2][2][4];   // [limb][mi]
                uint32_t bf[2][4][2];   // [limb][ni]
#pragma unroll
                for (int mi = 0; mi < 2; mi++) {
                    int row = wr * 32 + mi * 16 + a_row;
                    uint32_t off = SWZ128((uint32_t)(row * 128 + (ks * 2 + a_sel) * 16));
                    ldmx4(af[0][mi], A0 + off);
                    ldmx4(af[1][mi], A1 + off);
                }
#pragma unroll
                for (int nb = 0; nb < 4; nb += 2) {
                    int row = wc * 32 + (nb + (b_g >> 1)) * 8 + b_row;
                    uint32_t off = SWZ128((uint32_t)(row * 128 + (ks * 2 + (b_g & 1)) * 16));
                    uint32_t r4[4];
                    ldmx4(r4, B0 + off);
                    bf[0][nb][0] = r4[0]; bf[0][nb][1] = r4[1];
                    bf[0][nb + 1][0] = r4[2]; bf[0][nb + 1][1] = r4[3];
                    ldmx4(r4, B1 + off);
                    bf[1][nb][0] = r4[0]; bf[1][nb][1] = r4[1];
                    bf[1][nb + 1][0] = r4[2]; bf[1][nb + 1][1] = r4[3];
                }
                // 3 limb products: 00, 01, 10
#pragma unroll
                for (int mi = 0; mi < 2; mi++)
#pragma unroll
                    for (int ni = 0; ni < 4; ni++) {
                        mma_f16(acc[mi][ni], af[0][mi], bf[0][ni]);
                        mma_f16(acc[mi][ni], af[0][mi], bf[1][ni]);
                        mma_f16(acc[mi][ni], af[1][mi], bf[0][ni]);
                    }
            }
            __syncthreads();           // all reads of `buf` done before refill
        }

        // ---- epilogue: stage D (128x64, pitch 65) and scan; sibling CTA overlaps ----
        if (tid < NT) sinv[tid] = g_invn[c0 + tid];
#pragma unroll
        for (int mi = 0; mi < 2; mi++) {
            int R0 = wr * 32 + mi * 16 + (lane >> 2);
#pragma unroll
            for (int ni = 0; ni < 4; ni++) {
                int Cc = wc * 32 + ni * 8 + 2 * (lane & 3);
                stagef[R0 * STAGE_PITCH + Cc]           = acc[mi][ni][0];
                stagef[R0 * STAGE_PITCH + Cc + 1]       = acc[mi][ni][1];
                stagef[(R0 + 8) * STAGE_PITCH + Cc]     = acc[mi][ni][2];
                stagef[(R0 + 8) * STAGE_PITCH + Cc + 1] = acc[mi][ni][3];
            }
        }
        __syncthreads();

        {
            const int row = tid & 127;
            const int ch  = tid >> 7;            // col half 0/1 (32 cols)
            const float* rowp = stagef + row * STAGE_PITCH + ch * 32;
            const float* sp   = sinv + ch * 32;
#pragma unroll 4
            for (int j = 0; j < 32; j++) {
                int gc = c0 + ch * 32 + j;
                if (gc < C) top4_insert(rowp[j] * sp[j], gc, tv, ti);
            }
        }
        __syncthreads();   // staging fully read before next tile's loads overwrite it
    }

    // ---- write per-(query, slice, col-half) top-4 partials ----
    {
        const int row = tid & 127;
        const int ch  = tid >> 7;
        const int q   = mt * MT + row;
        if (q < FRM) {
            size_t base = (((size_t)q * NSLICE + sl) * 2 + ch) * KSEL;
#pragma unroll
            for (int p = 0; p < KSEL; p++) { g_pv[base + p] = tv[p]; g_pi[base + p] = ti[p]; }
        }
    }
}

// ---------------- kernel 3: merge partials, gather synth rows, average ----------------
__global__ void merge_gather_kernel(const float* __restrict__ S, float* __restrict__ out,
                                    int FRM, int C) {
    __shared__ float sv[32 * KSEL];
    __shared__ int   si[32 * KSEL];
    __shared__ int   fidx[KSEL];

    const int q   = blockIdx.x;
    const int tid = threadIdx.x;
    const int E   = NSLICE * 2 * KSEL;   // 304 partial entries per query

    if (tid < 32) {
        float v[KSEL]; int ix[KSEL];
#pragma unroll
        for (int p = 0; p < KSEL; p++) { v[p] = -3.4e38f; ix[p] = 0; }
        const size_t base = (size_t)q * E;
        for (int e = tid; e < E; e += 32)
            top4_insert(g_pv[base + e], g_pi[base + e], v, ix);
#pragma unroll
        for (int p = 0; p < KSEL; p++) { sv[tid * KSEL + p] = v[p]; si[tid * KSEL + p] = ix[p]; }
    }
    __syncthreads();
    if (tid == 0) {
        float v[KSEL]; int ix[KSEL];
#pragma unroll
        for (int p = 0; p < KSEL; p++) { v[p] = -3.4e38f; ix[p] = 0; }
        for (int e = 0; e < 32 * KSEL; e++) top4_insert(sv[e], si[e], v, ix);
#pragma unroll
        for (int p = 0; p < KSEL; p++) fidx[p] = ix[p];
    }
    __syncthreads();

    const float4* s0 = (const float4*)(S + (size_t)fidx[0] * F_DIM);
    const float4* s1 = (const float4*)(S + (size_t)fidx[1] * F_DIM);
    const float4* s2 = (const float4*)(S + (size_t)fidx[2] * F_DIM);
    const float4* s3 = (const float4*)(S + (size_t)fidx[3] * F_DIM);
    float4* o = (float4*)(out + (size_t)q * F_DIM);

    for (int pos = tid; pos < F_DIM / 4; pos += blockDim.x) {
        float4 a = s0[pos], b = s1[pos], c = s2[pos], d = s3[pos];
        float4 r;
        r.x = (a.x + b.x + c.x + d.x) * 0.25f;
        r.y = (a.y + b.y + c.y + d.y) * 0.25f;
        r.z = (a.z + b.z + c.z + d.z) * 0.25f;
        r.w = (a.w + b.w + c.w + d.w) * 0.25f;
        o[pos] = r;
    }
}

// ---------------- launch ----------------
extern "C" void kernel_launch(void* const* d_in, const int* in_sizes, int n_in,
                              void* d_out, int out_size) {
    const float* Q = (const float*)d_in[0];   // query_seq    (FRM, F)
    const float* M = (const float*)d_in[1];   // matching_set (C, F)
    const float* S = (const float*)d_in[2];   // synth_set    (C, F)
    float* out = (float*)d_out;

    const int FRM = in_sizes[0] / F_DIM;
    const int C   = in_sizes[1] / F_DIM;

    cudaFuncSetAttribute(knn_mma_kernel, cudaFuncAttributeMaxDynamicSharedMemorySize, SMEM_DYN);

    norms_kernel<<<(C + 7) / 8, 256>>>(M, C);

    __half *q0, *b0;
    cudaGetSymbolAddress((void**)&q0, g_qs);
    cudaGetSymbolAddress((void**)&b0, g_bs);
    __half *q1 = q0 + (size_t)FRM_MAX * F_DIM;
    __half *b1 = b0 + (size_t)C_MAX * F_DIM;

    size_t nm4 = (size_t)C * F_DIM / 4;
    size_t nq4 = (size_t)FRM * F_DIM / 4;
    split_kernel<<<(unsigned)((nm4 + 255) / 256), 256>>>(M, b0, b1, nm4);
    split_kernel<<<(unsigned)((nq4 + 255) / 256), 256>>>(Q, q0, q1, nq4);

    dim3 g2((FRM + MT - 1) / MT, NSLICE);
    knn_mma_kernel<<<g2, NTHREADS, SMEM_DYN>>>(FRM, C);

    merge_gather_kernel<<<FRM, 256>>>(S, out, FRM, C);
}

// round 17
// speedup vs baseline: 4.0990x; 1.0250x over previous
#include <cuda_runtime.h>
#include <cuda_fp16.h>
#include <cstdint>

// ---------------- problem constants ----------------
#define F_DIM   1024
#define KSEL    4
#define FRM_MAX 2048
#define C_MAX   100352

// ---------------- mma tiling ----------------
#define MT      128             // queries per CTA tile
#define NT      64              // candidates per CTA tile (2 CTAs/SM)
#define KC      64              // K elems per smem chunk (64 fp16 = 128B row)
#define NSLICE  38              // 16 x 38 = 608 CTAs = 2 waves at 2 CTA/SM
#define A_T_B   (128 * 128)     // 16KB per A limb tile
#define B_T_B   (64 * 128)      // 8KB per B limb tile
#define STAGE_B (2 * A_T_B + 2 * B_T_B)   // 48KB per pipeline stage
#define SMEM_DYN (2 * STAGE_B + 1024)
#define STAGE_PITCH 65          // f32 pitch for 128x64 epilogue staging
#define NTHREADS 256            // 8 warps; 2 CTAs/SM -> 4 warps/SMSP

#define SWZ128(off) ((off) ^ (((off) >> 3) & 0x70))

// ---------------- device scratch (static: no allocations allowed) ----------------
__device__ float  g_invn[C_MAX];
__device__ __half g_qs[2][(size_t)FRM_MAX * F_DIM];   // Q fp16 limbs
__device__ __half g_bs[2][(size_t)C_MAX * F_DIM];     // M fp16 limbs (tail rows 0)
__device__ float g_pv[(size_t)FRM_MAX * NSLICE * 2 * KSEL];  // 2 col-halves/slice
__device__ int   g_pi[(size_t)FRM_MAX * NSLICE * 2 * KSEL];

// ---------------- helpers ----------------
__device__ __forceinline__ uint32_t smem_u32(const void* p) {
    return (uint32_t)__cvta_generic_to_shared(p);
}
__device__ __forceinline__ void cp16(uint32_t dst, const void* src) {
    asm volatile("cp.async.cg.shared.global [%0], [%1], 16;" :: "r"(dst), "l"(src));
}
__device__ __forceinline__ void cp_commit() { asm volatile("cp.async.commit_group;" ::); }
__device__ __forceinline__ void cp_wait0()  { asm volatile("cp.async.wait_group 0;" ::: "memory"); }
__device__ __forceinline__ void cp_wait1()  { asm volatile("cp.async.wait_group 1;" ::: "memory"); }

__device__ __forceinline__ void ldmx4(uint32_t* r, uint32_t addr) {
    asm volatile("ldmatrix.sync.aligned.m8n8.x4.shared.b16 {%0,%1,%2,%3}, [%4];"
                 : "=r"(r[0]), "=r"(r[1]), "=r"(r[2]), "=r"(r[3]) : "r"(addr));
}
__device__ __forceinline__ void mma_f16(float d[4], const uint32_t a[4], const uint32_t b[2]) {
    asm volatile("mma.sync.aligned.m16n8k16.row.col.f32.f16.f16.f32 "
                 "{%0,%1,%2,%3}, {%4,%5,%6,%7}, {%8,%9}, {%0,%1,%2,%3};"
                 : "+f"(d[0]), "+f"(d[1]), "+f"(d[2]), "+f"(d[3])
                 : "r"(a[0]), "r"(a[1]), "r"(a[2]), "r"(a[3]), "r"(b[0]), "r"(b[1]));
}

__device__ __forceinline__ void top4_insert(float s, int c, float v[KSEL], int ix[KSEL]) {
#pragma unroll
    for (int p = 0; p < KSEL; p++) {
        if (s > v[p]) {
#pragma unroll
            for (int q = KSEL - 1; q > p; q--) { v[q] = v[q - 1]; ix[q] = ix[q - 1]; }
            v[p] = s; ix[p] = c;
            break;
        }
    }
}

// ---------------- kernel 0: 2-limb fp16 split ----------------
__global__ void split_kernel(const float* __restrict__ X,
                             __half* __restrict__ d0,
                             __half* __restrict__ d1, size_t n4) {
    size_t i = (size_t)blockIdx.x * blockDim.x + threadIdx.x;
    if (i >= n4) return;
    float4 x = ((const float4*)X)[i];
    const float* xs = (const float*)&x;
    __half h0[4], h1[4];
#pragma unroll
    for (int j = 0; j < 4; j++) {
        float v = xs[j];
        __half a0 = __float2half_rn(v);
        float r1 = v - __half2float(a0);
        h0[j] = a0;
        h1[j] = __float2half_rn(r1);
    }
    __half2* p0 = (__half2*)d0 + i * 2;
    __half2* p1 = (__half2*)d1 + i * 2;
    __half2 t;
    t.x = h0[0]; t.y = h0[1]; p0[0] = t;  t.x = h0[2]; t.y = h0[3]; p0[1] = t;
    t.x = h1[0]; t.y = h1[1]; p1[0] = t;  t.x = h1[2]; t.y = h1[3]; p1[1] = t;
}

// ---------------- kernel 1: inverse norms ----------------
__global__ void norms_kernel(const float* __restrict__ M, int C) {
    int row  = blockIdx.x * 8 + (threadIdx.x >> 5);
    int lane = threadIdx.x & 31;
    if (row >= C) return;
    const float4* p = (const float4*)(M + (size_t)row * F_DIM);
    float s = 0.f;
#pragma unroll
    for (int i = 0; i < F_DIM / 4 / 32; i++) {
        float4 v = p[lane + i * 32];
        s += v.x * v.x + v.y * v.y + v.z * v.z + v.w * v.w;
    }
#pragma unroll
    for (int o = 16; o > 0; o >>= 1) s += __shfl_xor_sync(0xffffffffu, s, o);
    if (lane == 0) g_invn[row] = rsqrtf(s);
}

// ---------------- kernel 2: mma.sync fp16x3 GEMM, 2 CTAs/SM, fused top-4 ----------------
__global__ void __launch_bounds__(NTHREADS, 2)
knn_mma_kernel(int FRM, int C) {
    extern __shared__ __align__(16) char dsm[];
    __shared__ float sinv[NT];

    const int tid  = threadIdx.x;
    const int wid  = tid >> 5;
    const int lane = tid & 31;
    const int wr   = wid >> 1;        // warp row (0..3) -> 32 query rows
    const int wc   = wid & 1;         // warp col (0..1) -> 32 candidate cols
    const int mt   = blockIdx.x;
    const int sl   = blockIdx.y;

    const uint32_t dsm_u    = smem_u32(dsm);
    const uint32_t tilebase = (dsm_u + 1023u) & ~1023u;
    // epilogue staging lives in the STAGE-1 region so next-tile chunk-0
    // prefetch (stage 0) can overlap the epilogue
    float* stagef = (float*)(dsm + (tilebase - dsm_u) + STAGE_B);

    const int tiles_total = (C + NT - 1) / NT;
    const int t0 = (int)((long long)sl       * tiles_total / NSLICE);
    const int t1 = (int)((long long)(sl + 1) * tiles_total / NSLICE);

    // ldmatrix lane address components
    const int a_row = lane & 15;            // A: row within m16 tile
    const int a_sel = lane >> 4;            // A: k-half unit
    const int b_g   = lane >> 3;            // B x4: lane group 0-3
    const int b_row = lane & 7;             // B: row within n8 tile

    // per-thread loader coords (hoisted)
    const int l_row8 = tid >> 3;            // 0..31
    const int l_c16  = tid & 7;

    // ---- slab loader: chunk kc of the tile starting at candidate c0x ----
    auto load_slab = [&](int c0x, int kc, int buf) {
        const uint32_t bb = tilebase + (uint32_t)buf * STAGE_B;
#pragma unroll
        for (int t = 0; t < 8; t++) {
            int tile = t >> 2;
            int row  = l_row8 + (t & 3) * 32;
            uint32_t dst = bb + (uint32_t)tile * A_T_B
                         + SWZ128((uint32_t)(row * 128 + l_c16 * 16));
            int qr = mt * MT + row; if (qr >= FRM) qr = FRM - 1;
            cp16(dst, &g_qs[tile][(size_t)qr * F_DIM + kc * KC + l_c16 * 8]);
        }
#pragma unroll
        for (int t = 0; t < 4; t++) {
            int tile = t >> 1;
            int row  = l_row8 + (t & 1) * 32;
            uint32_t dst = bb + 2 * A_T_B + (uint32_t)tile * B_T_B
                         + SWZ128((uint32_t)(row * 128 + l_c16 * 16));
            cp16(dst, &g_bs[tile][(size_t)(c0x + row) * F_DIM + kc * KC + l_c16 * 8]);
        }
        cp_commit();
    };

    // running top-4: thread owns (query row tid&127, col-half tid>>7)
    float tv[KSEL]; int ti[KSEL];
#pragma unroll
    for (int p = 0; p < KSEL; p++) { tv[p] = -3.4e38f; ti[p] = 0; }

    // prologue: first tile's chunk 0 in flight before the tile loop
    if (t0 < t1) load_slab(t0 * NT, 0, 0);

    for (int ct = t0; ct < t1; ct++) {
        const int c0 = ct * NT;

        // accumulators: 2 m16 x 4 n8 per warp (32x32 warp tile)
        float acc[2][4][4];
#pragma unroll
        for (int mi = 0; mi < 2; mi++)
#pragma unroll
            for (int ni = 0; ni < 4; ni++)
#pragma unroll
                for (int r = 0; r < 4; r++) acc[mi][ni][r] = 0.f;

        const int NKC = F_DIM / KC;   // 16
        for (int kc = 0; kc < NKC; kc++) {
            const int buf = kc & 1;
            // issue next slab: next chunk, or NEXT TILE's chunk 0 (stage 0 free:
            // it was last read at kc-1)
            bool issued = true;
            if (kc + 1 < NKC)      load_slab(c0, kc + 1, buf ^ 1);
            else if (ct + 1 < t1)  load_slab((ct + 1) * NT, 0, buf ^ 1);
            else                   issued = false;
            if (issued) cp_wait1(); else cp_wait0();
            __syncthreads();           // slab `buf` visible to all warps

            const uint32_t bb = tilebase + (uint32_t)buf * STAGE_B;
            const uint32_t A0 = bb;
            const uint32_t A1 = bb + A_T_B;
            const uint32_t B0 = bb + 2 * A_T_B;
            const uint32_t B1 = bb + 2 * A_T_B + B_T_B;

#pragma unroll
            for (int s = 0; s < 4; s++) {
                // per-warp k-step stagger: desynchronizes LDSM bursts across warps
                const int ks = (s + wid) & 3;
                uint32_t af[2][2][4];   // [limb][mi]
                uint32_t bf[2][4][2];   // [limb][ni]
#pragma unroll
                for (int mi = 0; mi < 2; mi++) {
                    int row = wr * 32 + mi * 16 + a_row;
                    uint32_t off = SWZ128((uint32_t)(row * 128 + (ks * 2 + a_sel) * 16));
                    ldmx4(af[0][mi], A0 + off);
                    ldmx4(af[1][mi], A1 + off);
                }
#pragma unroll
                for (int nb = 0; nb < 4; nb += 2) {
                    int row = wc * 32 + (nb + (b_g >> 1)) * 8 + b_row;
                    uint32_t off = SWZ128((uint32_t)(row * 128 + (ks * 2 + (b_g & 1)) * 16));
                    uint32_t r4[4];
                    ldmx4(r4, B0 + off);
                    bf[0][nb][0] = r4[0]; bf[0][nb][1] = r4[1];
                    bf[0][nb + 1][0] = r4[2]; bf[0][nb + 1][1] = r4[3];
                    ldmx4(r4, B1 + off);
                    bf[1][nb][0] = r4[0]; bf[1][nb][1] = r4[1];
                    bf[1][nb + 1][0] = r4[2]; bf[1][nb + 1][1] = r4[3];
                }
                // product-OUTER ordering: 8 independent HMMAs between any two
                // that touch the same accumulator (kills dependent chains)
#pragma unroll
                for (int mi = 0; mi < 2; mi++)
#pragma unroll
                    for (int ni = 0; ni < 4; ni++)
                        mma_f16(acc[mi][ni], af[0][mi], bf[0][ni]);
#pragma unroll
                for (int mi = 0; mi < 2; mi++)
#pragma unroll
                    for (int ni = 0; ni < 4; ni++)
                        mma_f16(acc[mi][ni], af[0][mi], bf[1][ni]);
#pragma unroll
                for (int mi = 0; mi < 2; mi++)
#pragma unroll
                    for (int ni = 0; ni < 4; ni++)
                        mma_f16(acc[mi][ni], af[1][mi], bf[0][ni]);
            }
            __syncthreads();           // all reads of `buf` done before refill
        }

        // ---- epilogue in stage-1 region (stage 0 holds next tile's prefetch) ----
        if (tid < NT) sinv[tid] = g_invn[c0 + tid];
#pragma unroll
        for (int mi = 0; mi < 2; mi++) {
            int R0 = wr * 32 + mi * 16 + (lane >> 2);
#pragma unroll
            for (int ni = 0; ni < 4; ni++) {
                int Cc = wc * 32 + ni * 8 + 2 * (lane & 3);
                stagef[R0 * STAGE_PITCH + Cc]           = acc[mi][ni][0];
                stagef[R0 * STAGE_PITCH + Cc + 1]       = acc[mi][ni][1];
                stagef[(R0 + 8) * STAGE_PITCH + Cc]     = acc[mi][ni][2];
                stagef[(R0 + 8) * STAGE_PITCH + Cc + 1] = acc[mi][ni][3];
            }
        }
        __syncthreads();

        {
            const int row = tid & 127;
            const int ch  = tid >> 7;            // col half 0/1 (32 cols)
            const float* rowp = stagef + row * STAGE_PITCH + ch * 32;
            const float* sp   = sinv + ch * 32;
#pragma unroll 4
            for (int j = 0; j < 32; j++) {
                int gc = c0 + ch * 32 + j;
                if (gc < C) top4_insert(rowp[j] * sp[j], gc, tv, ti);
            }
        }
        __syncthreads();   // staging fully read before next tile overwrites stage 1
    }

    // ---- write per-(query, slice, col-half) top-4 partials ----
    {
        const int row = tid & 127;
        const int ch  = tid >> 7;
        const int q   = mt * MT + row;
        if (q < FRM) {
            size_t base = (((size_t)q * NSLICE + sl) * 2 + ch) * KSEL;
#pragma unroll
            for (int p = 0; p < KSEL; p++) { g_pv[base + p] = tv[p]; g_pi[base + p] = ti[p]; }
        }
    }
}

// ---------------- kernel 3: merge partials, gather synth rows, average ----------------
__global__ void merge_gather_kernel(const float* __restrict__ S, float* __restrict__ out,
                                    int FRM, int C) {
    __shared__ float sv[32 * KSEL];
    __shared__ int   si[32 * KSEL];
    __shared__ int   fidx[KSEL];

    const int q   = blockIdx.x;
    const int tid = threadIdx.x;
    const int E   = NSLICE * 2 * KSEL;   // 304 partial entries per query

    if (tid < 32) {
        float v[KSEL]; int ix[KSEL];
#pragma unroll
        for (int p = 0; p < KSEL; p++) { v[p] = -3.4e38f; ix[p] = 0; }
        const size_t base = (size_t)q * E;
        for (int e = tid; e < E; e += 32)
            top4_insert(g_pv[base + e], g_pi[base + e], v, ix);
#pragma unroll
        for (int p = 0; p < KSEL; p++) { sv[tid * KSEL + p] = v[p]; si[tid * KSEL + p] = ix[p]; }
    }
    __syncthreads();
    if (tid == 0) {
        float v[KSEL]; int ix[KSEL];
#pragma unroll
        for (int p = 0; p < KSEL; p++) { v[p] = -3.4e38f; ix[p] = 0; }
        for (int e = 0; e < 32 * KSEL; e++) top4_insert(sv[e], si[e], v, ix);
#pragma unroll
        for (int p = 0; p < KSEL; p++) fidx[p] = ix[p];
    }
    __syncthreads();

    const float4* s0 = (const float4*)(S + (size_t)fidx[0] * F_DIM);
    const float4* s1 = (const float4*)(S + (size_t)fidx[1] * F_DIM);
    const float4* s2 = (const float4*)(S + (size_t)fidx[2] * F_DIM);
    const float4* s3 = (const float4*)(S + (size_t)fidx[3] * F_DIM);
    float4* o = (float4*)(out + (size_t)q * F_DIM);

    for (int pos = tid; pos < F_DIM / 4; pos += blockDim.x) {
        float4 a = s0[pos], b = s1[pos], c = s2[pos], d = s3[pos];
        float4 r;
        r.x = (a.x + b.x + c.x + d.x) * 0.25f;
        r.y = (a.y + b.y + c.y + d.y) * 0.25f;
        r.z = (a.z + b.z + c.z + d.z) * 0.25f;
        r.w = (a.w + b.w + c.w + d.w) * 0.25f;
        o[pos] = r;
    }
}

// ---------------- launch ----------------
extern "C" void kernel_launch(void* const* d_in, const int* in_sizes, int n_in,
                              void* d_out, int out_size) {
    const float* Q = (const float*)d_in[0];   // query_seq    (FRM, F)
    const float* M = (const float*)d_in[1];   // matching_set (C, F)
    const float* S = (const float*)d_in[2];   // synth_set    (C, F)
    float* out = (float*)d_out;

    const int FRM = in_sizes[0] / F_DIM;
    const int C   = in_sizes[1] / F_DIM;

    cudaFuncSetAttribute(knn_mma_kernel, cudaFuncAttributeMaxDynamicSharedMemorySize, SMEM_DYN);

    norms_kernel<<<(C + 7) / 8, 256>>>(M, C);

    __half *q0, *b0;
    cudaGetSymbolAddress((void**)&q0, g_qs);
    cudaGetSymbolAddress((void**)&b0, g_bs);
    __half *q1 = q0 + (size_t)FRM_MAX * F_DIM;
    __half *b1 = b0 + (size_t)C_MAX * F_DIM;

    size_t nm4 = (size_t)C * F_DIM / 4;
    size_t nq4 = (size_t)FRM * F_DIM / 4;
    split_kernel<<<(unsigned)((nm4 + 255) / 256), 256>>>(M, b0, b1, nm4);
    split_kernel<<<(unsigned)((nq4 + 255) / 256), 256>>>(Q, q0, q1, nq4);

    dim3 g2((FRM + MT - 1) / MT, NSLICE);
    knn_mma_kernel<<<g2, NTHREADS, SMEM_DYN>>>(FRM, C);

    merge_gather_kernel<<<FRM, 256>>>(S, out, FRM, C);
}